// round 13
// baseline (speedup 1.0000x reference)
#include <cuda_runtime.h>

#define NB 4
#define NQS 512
#define NKS 1024
#define DD 64
#define NCTAS 1024

typedef unsigned long long ull;

#define ADD2(o,a,b)   asm("add.rn.f32x2 %0, %1, %2;" : "=l"(o) : "l"(a), "l"(b))
#define FMA2(o,a,b,c) asm("fma.rn.f32x2 %0, %1, %2, %3;" : "=l"(o) : "l"(a), "l"(b), "l"(c))
#define PACKDUP(o,f)  asm("mov.b64 %0, {%1, %1};" : "=l"(o) : "f"(f))
#define ABSM 0x7FFFFFFF7FFFFFFFULL

// ---- attn-phase smem (floats) ----
#define S_STRIDE 260
#define QD_OFF   2080              // [2 halves][64 d][8] = 1024
#define RED_OFF  2080              // aliases QD (dead after logits)
#define MP_OFF   4128              // [8][2] warp-pair maxima
#define FLAG_OFF 4160              // 1 int: last-CTA flag
// mlp phase needs 5264 floats -> 21056 B total (the max)
#define SMEM_BYTES 21056

// Scratch: k transposed per batch (kT[b][d][j]); q row-major.
__device__ __align__(16) float g_kT[NB * DD * NKS];
__device__ __align__(16) float g_q [NB * NQS * DD];
// split-K partials: per (b,qt,ks) CTA: o[8][64], m[8], s[8]
__device__ __align__(16) float g_po[NCTAS * 512];
__device__ float g_pm[NCTAS * 8];
__device__ float g_ps[NCTAS * 8];
// per-(b,qt) group completion counters (reset by combiner -> replay-safe)
__device__ int g_done[256];

// grid barrier (replay-safe: g_cnt self-resets, g_sense monotonic)
__device__ unsigned g_cnt   = 0;
__device__ unsigned g_sense = 0;

__device__ __forceinline__ void grid_barrier(int t)
{
    __syncthreads();
    if (t == 0) {
        unsigned s = *(volatile unsigned*)&g_sense;
        __threadfence();
        if (atomicAdd(&g_cnt, 1) == NCTAS - 1) {
            g_cnt = 0;
            __threadfence();
            atomicAdd(&g_sense, 1);
        } else {
            while (*(volatile unsigned*)&g_sense == s) { __nanosleep(32); }
            __threadfence();
        }
    }
    __syncthreads();
}

// occupancy 7: reg budget 73 (vs 64 at occ 8); capacity 148*7=1036 >= 1024,
// so the grid barrier stays deadlock-free with all CTAs wave-1 resident.
__global__ __launch_bounds__(128, 7) void fused_kernel(
    const float* __restrict__ x1, const float* __restrict__ x2,
    const float* __restrict__ rv,
    const float* __restrict__ Wk1, const float* __restrict__ bk1,
    const float* __restrict__ Wk2, const float* __restrict__ bk2,
    const float* __restrict__ Wq1, const float* __restrict__ bq1,
    const float* __restrict__ Wq2, const float* __restrict__ bq2,
    float* __restrict__ out)
{
    extern __shared__ float sm[];
    const int bid  = blockIdx.x;
    const int t    = threadIdx.x;
    const int lane = t & 31;
    const int w    = t >> 5;

    // =============== Phase A: MLPs (768 CTAs x 8 rows) =====================
    if (bid < 768) {
        float* Ws  = sm;             // 4096 (W1, then W2)
        float* b1s = sm + 4096;
        float* b2s = sm + 4160;
        float* xs  = sm + 4224;      // 8*65
        float* hs  = sm + 4744;      // 8*65

        const bool keypath = bid < 512;
        const float *x, *W1, *b1, *W2, *b2;
        int row0;
        if (keypath) { x = x1; W1 = Wk1; b1 = bk1; W2 = Wk2; b2 = bk2; row0 = bid * 8; }
        else         { x = x2; W1 = Wq1; b1 = bq1; W2 = Wq2; b2 = bq2; row0 = (bid - 512) * 8; }

        for (int idx = t; idx < 1024; idx += 128)
            ((float4*)Ws)[idx] = ((const float4*)W1)[idx];
        if (t < 16) {
            ((float4*)b1s)[t] = ((const float4*)b1)[t];
            ((float4*)b2s)[t] = ((const float4*)b2)[t];
        }
        {
            int rr = t >> 4, c = t & 15;
            float4 v = ((const float4*)(x + (size_t)(row0 + rr) * DD))[c];
            xs[rr * 65 + c * 4 + 0] = v.x;
            xs[rr * 65 + c * 4 + 1] = v.y;
            xs[rr * 65 + c * 4 + 2] = v.z;
            xs[rr * 65 + c * 4 + 3] = v.w;
        }
        __syncthreads();

        const int row = t >> 4, sl = t & 15;

        float4 acc = ((const float4*)b1s)[sl];
        {
            const float* in1 = xs + row * 65;
#pragma unroll 8
            for (int din = 0; din < 64; din++) {
                float xv = in1[din];
                float4 wv = ((const float4*)Ws)[din * 16 + sl];
                acc.x = fmaf(xv, wv.x, acc.x);
                acc.y = fmaf(xv, wv.y, acc.y);
                acc.z = fmaf(xv, wv.z, acc.z);
                acc.w = fmaf(xv, wv.w, acc.w);
            }
        }
        {
            float* h = hs + row * 65 + sl * 4;
            h[0] = fmaxf(acc.x, 0.f); h[1] = fmaxf(acc.y, 0.f);
            h[2] = fmaxf(acc.z, 0.f); h[3] = fmaxf(acc.w, 0.f);
        }
        __syncthreads();

        for (int idx = t; idx < 1024; idx += 128)
            ((float4*)Ws)[idx] = ((const float4*)W2)[idx];
        __syncthreads();

        acc = ((const float4*)b2s)[sl];
        {
            const float* in2 = hs + row * 65;
#pragma unroll 8
            for (int din = 0; din < 64; din++) {
                float xv = in2[din];
                float4 wv = ((const float4*)Ws)[din * 16 + sl];
                acc.x = fmaf(xv, wv.x, acc.x);
                acc.y = fmaf(xv, wv.y, acc.y);
                acc.z = fmaf(xv, wv.z, acc.z);
                acc.w = fmaf(xv, wv.w, acc.w);
            }
        }

        if (keypath) {
            __syncthreads();
            {
                float* o = xs + row * 65 + sl * 4;
                o[0] = acc.x; o[1] = acc.y; o[2] = acc.z; o[3] = acc.w;
            }
            __syncthreads();
            const int bb = row0 >> 10;
            const int j0 = row0 & 1023;
            float* o = g_kT + (size_t)bb * DD * NKS + j0;
#pragma unroll
            for (int u = 0; u < 4; u++) {
                int idx = u * 128 + t;
                int d = idx >> 3, j = idx & 7;
                o[(size_t)d * NKS + j] = xs[j * 65 + d];
            }
        } else {
            const int rg = row0 + row;
            ((float4*)(g_q + (size_t)rg * DD))[sl] = acc;
        }
    }

    grid_barrier(t);   // g_kT / g_q complete

    // =============== Phase B: split-K attention ============================
    // CTA = (b, 8-query tile qt, key-quarter ks): bid = ((b*64)+qt)*4 + ks
    float* S  = sm;             // [8][260] logits -> P in place
    float* QD = sm + QD_OFF;    // [2][64][8] (-q dup), dead after logits
    float* RED= sm + RED_OFF;   // aliases QD
    float* Mp = sm + MP_OFF;    // [8][2]
    int*   FL = (int*)(sm + FLAG_OFF);

    const int b  = bid >> 8;
    const int qt = (bid >> 2) & 63;
    const int ks = bid & 3;
    const int group = bid >> 2;        // (b,qt) in [0,256)

    // stage QD[q>>2][d][2(q&3)..] = -q[qt*8+q][d]
#pragma unroll
    for (int u = 0; u < 4; u++) {
        int idx = u * 128 + t;          // 0..511
        int q = idx & 7, d = idx >> 3;
        float v = g_q[(size_t)(b * NQS + qt * 8 + q) * DD + d];
        float* dst = QD + (q >> 2) * 512 + d * 8 + 2 * (q & 3);
        dst[0] = -v;
        dst[1] = -v;
    }
    __syncthreads();

    // -------- logits: warp = (query-half, 128-key span), 2 LDG chains -----
    {
        const int qh    = w & 1;            // queries qh*4 .. qh*4+3
        const int kbase = (w >> 1) * 128;   // local keys kbase..kbase+127
        const int jA = kbase + 2 * lane;
        const int jB = jA + 64;
        const float* kpA = g_kT + (size_t)b * DD * NKS + ks * 256 + jA;
        const float* kpB = kpA + 64;
        const float* QDh = QD + qh * 512;

        ull aA0=0,aA1=0,aA2=0,aA3=0,aB0=0,aB1=0,aB2=0,aB3=0;
#pragma unroll 8
        for (int d = 0; d < 64; d++) {
            ull kA = *(const ull*)(kpA + (size_t)d * NKS);
            ull kB = *(const ull*)(kpB + (size_t)d * NKS);
            ulonglong2 n01 = *(const ulonglong2*)(QDh + d * 8);
            ulonglong2 n23 = *(const ulonglong2*)(QDh + d * 8 + 4);
            ull u_;
            ADD2(u_, kA, n01.x); u_ &= ABSM; ADD2(aA0, aA0, u_);
            ADD2(u_, kA, n01.y); u_ &= ABSM; ADD2(aA1, aA1, u_);
            ADD2(u_, kA, n23.x); u_ &= ABSM; ADD2(aA2, aA2, u_);
            ADD2(u_, kA, n23.y); u_ &= ABSM; ADD2(aA3, aA3, u_);
            ADD2(u_, kB, n01.x); u_ &= ABSM; ADD2(aB0, aB0, u_);
            ADD2(u_, kB, n01.y); u_ &= ABSM; ADD2(aB1, aB1, u_);
            ADD2(u_, kB, n23.x); u_ &= ABSM; ADD2(aB2, aB2, u_);
            ADD2(u_, kB, n23.y); u_ &= ABSM; ADD2(aB3, aB3, u_);
        }
        const ull accA[4] = {aA0, aA1, aA2, aA3};
        const ull accB[4] = {aB0, aB1, aB2, aB3};
        float m[4];
#pragma unroll
        for (int i = 0; i < 4; i++) {
            const int q = qh * 4 + i;
            ull a = accA[i], bu = accB[i];
            float fa0 = -__uint_as_float((unsigned)a);
            float fa1 = -__uint_as_float((unsigned)(a >> 32));
            float fb0 = -__uint_as_float((unsigned)bu);
            float fb1 = -__uint_as_float((unsigned)(bu >> 32));
            *(float2*)(S + q * S_STRIDE + jA) = make_float2(fa0, fa1);
            *(float2*)(S + q * S_STRIDE + jB) = make_float2(fb0, fb1);
            m[i] = fmaxf(fmaxf(fa0, fa1), fmaxf(fb0, fb1));
        }
#pragma unroll
        for (int i = 0; i < 4; i++) {
#pragma unroll
            for (int o = 16; o; o >>= 1)
                m[i] = fmaxf(m[i], __shfl_xor_sync(0xffffffffu, m[i], o));
        }
        if (lane == 0) {
#pragma unroll
            for (int i = 0; i < 4; i++) Mp[(qh * 4 + i) * 2 + (w >> 1)] = m[i];
        }
    }
    __syncthreads();

    // -------- local softmax in place; (M, sum) -> global partials ---------
#pragma unroll
    for (int rr = 0; rr < 2; rr++) {
        const int row = w * 2 + rr;
        const float M = fmaxf(Mp[row * 2 + 0], Mp[row * 2 + 1]);
        float* Srow = S + row * S_STRIDE;
        float sum = 0.f;
#pragma unroll
        for (int it = 0; it < 8; it++) {
            int j = it * 32 + lane;
            float p = __expf(Srow[j] - M);
            Srow[j] = p;
            sum += p;
        }
#pragma unroll
        for (int o = 16; o; o >>= 1) sum += __shfl_xor_sync(0xffffffffu, sum, o);
        if (lane == 0) {
            g_pm[bid * 8 + row] = M;
            g_ps[bid * 8 + row] = sum;
        }
    }
    __syncthreads();

    // -------- partial O = P @ r: float4-amortized P loads -----------------
    {
        const int dg = lane & 15;
        const int qh = lane >> 4;
        const float* rb = rv + ((size_t)b * NKS + ks * 256 + w * 64) * DD + dg * 4;
        const float* Sb = S + (qh * 4) * S_STRIDE + w * 64;

        ull c00=0,c01=0,c10=0,c11=0,c20=0,c21=0,c30=0,c31=0;
#pragma unroll 4
        for (int c4 = 0; c4 < 16; c4++) {
            float4 P0 = *(const float4*)(Sb + 0 * S_STRIDE + c4 * 4);
            float4 P1 = *(const float4*)(Sb + 1 * S_STRIDE + c4 * 4);
            float4 P2 = *(const float4*)(Sb + 2 * S_STRIDE + c4 * 4);
            float4 P3 = *(const float4*)(Sb + 3 * S_STRIDE + c4 * 4);
#pragma unroll
            for (int e = 0; e < 4; e++) {
                const int kk = c4 * 4 + e;
                ulonglong2 r2 = *(const ulonglong2*)(rb + (size_t)kk * DD);
                float p0 = (e == 0) ? P0.x : (e == 1) ? P0.y : (e == 2) ? P0.z : P0.w;
                float p1 = (e == 0) ? P1.x : (e == 1) ? P1.y : (e == 2) ? P1.z : P1.w;
                float p2 = (e == 0) ? P2.x : (e == 1) ? P2.y : (e == 2) ? P2.z : P2.w;
                float p3 = (e == 0) ? P3.x : (e == 1) ? P3.y : (e == 2) ? P3.z : P3.w;
                ull pd;
                PACKDUP(pd, p0); FMA2(c00, pd, r2.x, c00); FMA2(c01, pd, r2.y, c01);
                PACKDUP(pd, p1); FMA2(c10, pd, r2.x, c10); FMA2(c11, pd, r2.y, c11);
                PACKDUP(pd, p2); FMA2(c20, pd, r2.x, c20); FMA2(c21, pd, r2.y, c21);
                PACKDUP(pd, p3); FMA2(c30, pd, r2.x, c30); FMA2(c31, pd, r2.y, c31);
            }
        }
        float4* R4 = (float4*)RED;
        const ull cc[4][2] = {{c00,c01},{c10,c11},{c20,c21},{c30,c31}};
#pragma unroll
        for (int i = 0; i < 4; i++) {
            int q = qh * 4 + i;
            R4[w * 128 + q * 16 + dg] =
                make_float4(__uint_as_float((unsigned)cc[i][0]),
                            __uint_as_float((unsigned)(cc[i][0] >> 32)),
                            __uint_as_float((unsigned)cc[i][1]),
                            __uint_as_float((unsigned)(cc[i][1] >> 32)));
        }
    }
    __syncthreads();

    // reduce 4 warps, store raw partial o to global
    {
        const int q = t >> 4, dd = t & 15;
        float4* R4 = (float4*)RED;
        float4 s = R4[q * 16 + dd];
#pragma unroll
        for (int g = 1; g < 4; g++) {
            float4 v = R4[g * 128 + q * 16 + dd];
            s.x += v.x; s.y += v.y; s.z += v.z; s.w += v.w;
        }
        ((float4*)(g_po + (size_t)bid * 512 + q * 64))[dd] = s;
    }
    __syncthreads();

    // =============== last-CTA combine (proven in R10/R11) ==================
    if (t == 0) {
        __threadfence();
        FL[0] = (atomicAdd(&g_done[group], 1) == 3) ? 1 : 0;
    }
    __syncthreads();

    if (FL[0]) {
        const int bb = group >> 6, qq = group & 63;
        const int q = t >> 4, dd = t & 15;
        const int base = group * 4;

        float m0 = g_pm[(base + 0) * 8 + q];
        float m1 = g_pm[(base + 1) * 8 + q];
        float m2 = g_pm[(base + 2) * 8 + q];
        float m3 = g_pm[(base + 3) * 8 + q];
        float M = fmaxf(fmaxf(m0, m1), fmaxf(m2, m3));
        float w0 = __expf(m0 - M), w1 = __expf(m1 - M);
        float w2 = __expf(m2 - M), w3 = __expf(m3 - M);
        float denom = w0 * g_ps[(base + 0) * 8 + q] + w1 * g_ps[(base + 1) * 8 + q]
                    + w2 * g_ps[(base + 2) * 8 + q] + w3 * g_ps[(base + 3) * 8 + q];

        float4 o0 = ((const float4*)(g_po + (size_t)(base + 0) * 512 + q * 64))[dd];
        float4 o1 = ((const float4*)(g_po + (size_t)(base + 1) * 512 + q * 64))[dd];
        float4 o2 = ((const float4*)(g_po + (size_t)(base + 2) * 512 + q * 64))[dd];
        float4 o3 = ((const float4*)(g_po + (size_t)(base + 3) * 512 + q * 64))[dd];

        const float li = 1.0f / denom;
        float4 o;
        o.x = (w0 * o0.x + w1 * o1.x + w2 * o2.x + w3 * o3.x) * li;
        o.y = (w0 * o0.y + w1 * o1.y + w2 * o2.y + w3 * o3.y) * li;
        o.z = (w0 * o0.z + w1 * o1.z + w2 * o2.z + w3 * o3.z) * li;
        o.w = (w0 * o0.w + w1 * o1.w + w2 * o2.w + w3 * o3.w) * li;

        ((float4*)(out + (size_t)(bb * NQS + qq * 8 + q) * DD))[dd] = o;

        if (t == 0) g_done[group] = 0;   // reset for graph replay
    }
}

// ---------------------------------------------------------------------------
extern "C" void kernel_launch(void* const* d_in, const int* in_sizes, int n_in,
                              void* d_out, int out_size)
{
    const float* x1  = (const float*)d_in[0];
    const float* x2  = (const float*)d_in[1];
    const float* r   = (const float*)d_in[2];
    const float* Wk1 = (const float*)d_in[3];
    const float* bk1 = (const float*)d_in[4];
    const float* Wk2 = (const float*)d_in[5];
    const float* bk2 = (const float*)d_in[6];
    const float* Wq1 = (const float*)d_in[7];
    const float* bq1 = (const float*)d_in[8];
    const float* Wq2 = (const float*)d_in[9];
    const float* bq2 = (const float*)d_in[10];
    float* out = (float*)d_out;

    cudaFuncSetAttribute(fused_kernel, cudaFuncAttributeMaxDynamicSharedMemorySize,
                         SMEM_BYTES);

    fused_kernel<<<NCTAS, 128, SMEM_BYTES>>>(
        x1, x2, r, Wk1, bk1, Wk2, bk2, Wq1, bq1, Wq2, bq2, out);
}

// round 14
// speedup vs baseline: 1.5403x; 1.5403x over previous
#include <cuda_runtime.h>

#define NB 4
#define NQS 512
#define NKS 1024
#define DD 64
#define NCTAS 1024

typedef unsigned long long ull;

#define ADD2(o,a,b)   asm("add.rn.f32x2 %0, %1, %2;" : "=l"(o) : "l"(a), "l"(b))
#define FMA2(o,a,b,c) asm("fma.rn.f32x2 %0, %1, %2, %3;" : "=l"(o) : "l"(a), "l"(b), "l"(c))
#define PACKDUP(o,f)  asm("mov.b64 %0, {%1, %1};" : "=l"(o) : "f"(f))
#define ABSM 0x7FFFFFFF7FFFFFFFULL

// ---- attn-phase smem (floats) ----
#define S_STRIDE 260
#define QD_OFF   2080              // [64 d][16] = 1024
#define RED_OFF  2080              // aliases QD (dead after logits)
#define MP_OFF   4128              // [8][4] warp maxima
#define FLAG_OFF 4160              // 1 int: last-CTA flag
// mlp phase needs 5264 floats -> 21056 B total (the max)
#define SMEM_BYTES 21056

// Scratch: k transposed per batch (kT[b][d][j]); q row-major.
__device__ __align__(16) float g_kT[NB * DD * NKS];
__device__ __align__(16) float g_q [NB * NQS * DD];
// split-K partials: per (b,qt,ks) CTA: o[8][64], m[8], s[8]
__device__ __align__(16) float g_po[NCTAS * 512];
__device__ float g_pm[NCTAS * 8];
__device__ float g_ps[NCTAS * 8];
// per-(b,qt) group completion counters (reset by combiner -> replay-safe)
__device__ int g_done[256];

// grid barrier (replay-safe)
__device__ unsigned g_cnt   = 0;
__device__ unsigned g_sense = 0;

__device__ __forceinline__ void grid_barrier(int t)
{
    __syncthreads();
    if (t == 0) {
        unsigned s = *(volatile unsigned*)&g_sense;
        __threadfence();
        if (atomicAdd(&g_cnt, 1) == NCTAS - 1) {
            g_cnt = 0;
            __threadfence();
            atomicAdd(&g_sense, 1);
        } else {
            while (*(volatile unsigned*)&g_sense == s) { __nanosleep(32); }
            __threadfence();
        }
    }
    __syncthreads();
}

__global__ __launch_bounds__(128, 8) void fused_kernel(
    const float* __restrict__ x1, const float* __restrict__ x2,
    const float* __restrict__ rv,
    const float* __restrict__ Wk1, const float* __restrict__ bk1,
    const float* __restrict__ Wk2, const float* __restrict__ bk2,
    const float* __restrict__ Wq1, const float* __restrict__ bq1,
    const float* __restrict__ Wq2, const float* __restrict__ bq2,
    float* __restrict__ out)
{
    extern __shared__ float sm[];
    const int bid  = blockIdx.x;
    const int t    = threadIdx.x;
    const int lane = t & 31;
    const int w    = t >> 5;

    // =============== Phase A: MLPs (768 CTAs x 8 rows) =====================
    if (bid < 768) {
        float* Ws  = sm;             // 4096 (W1, then W2)
        float* b1s = sm + 4096;
        float* b2s = sm + 4160;
        float* xs  = sm + 4224;      // 8*65
        float* hs  = sm + 4744;      // 8*65

        const bool keypath = bid < 512;
        const float *x, *W1, *b1, *W2, *b2;
        int row0;
        if (keypath) { x = x1; W1 = Wk1; b1 = bk1; W2 = Wk2; b2 = bk2; row0 = bid * 8; }
        else         { x = x2; W1 = Wq1; b1 = bq1; W2 = Wq2; b2 = bq2; row0 = (bid - 512) * 8; }

        for (int idx = t; idx < 1024; idx += 128)
            ((float4*)Ws)[idx] = ((const float4*)W1)[idx];
        if (t < 16) {
            ((float4*)b1s)[t] = ((const float4*)b1)[t];
            ((float4*)b2s)[t] = ((const float4*)b2)[t];
        }
        {
            int rr = t >> 4, c = t & 15;
            float4 v = ((const float4*)(x + (size_t)(row0 + rr) * DD))[c];
            xs[rr * 65 + c * 4 + 0] = v.x;
            xs[rr * 65 + c * 4 + 1] = v.y;
            xs[rr * 65 + c * 4 + 2] = v.z;
            xs[rr * 65 + c * 4 + 3] = v.w;
        }
        __syncthreads();

        const int row = t >> 4, sl = t & 15;

        float4 acc = ((const float4*)b1s)[sl];
        {
            const float* in1 = xs + row * 65;
#pragma unroll 8
            for (int din = 0; din < 64; din++) {
                float xv = in1[din];
                float4 wv = ((const float4*)Ws)[din * 16 + sl];
                acc.x = fmaf(xv, wv.x, acc.x);
                acc.y = fmaf(xv, wv.y, acc.y);
                acc.z = fmaf(xv, wv.z, acc.z);
                acc.w = fmaf(xv, wv.w, acc.w);
            }
        }
        {
            float* h = hs + row * 65 + sl * 4;
            h[0] = fmaxf(acc.x, 0.f); h[1] = fmaxf(acc.y, 0.f);
            h[2] = fmaxf(acc.z, 0.f); h[3] = fmaxf(acc.w, 0.f);
        }
        __syncthreads();

        for (int idx = t; idx < 1024; idx += 128)
            ((float4*)Ws)[idx] = ((const float4*)W2)[idx];
        __syncthreads();

        acc = ((const float4*)b2s)[sl];
        {
            const float* in2 = hs + row * 65;
#pragma unroll 8
            for (int din = 0; din < 64; din++) {
                float xv = in2[din];
                float4 wv = ((const float4*)Ws)[din * 16 + sl];
                acc.x = fmaf(xv, wv.x, acc.x);
                acc.y = fmaf(xv, wv.y, acc.y);
                acc.z = fmaf(xv, wv.z, acc.z);
                acc.w = fmaf(xv, wv.w, acc.w);
            }
        }

        if (keypath) {
            __syncthreads();
            {
                float* o = xs + row * 65 + sl * 4;
                o[0] = acc.x; o[1] = acc.y; o[2] = acc.z; o[3] = acc.w;
            }
            __syncthreads();
            const int bb = row0 >> 10;
            const int j0 = row0 & 1023;
            float* o = g_kT + (size_t)bb * DD * NKS + j0;
#pragma unroll
            for (int u = 0; u < 4; u++) {
                int idx = u * 128 + t;
                int d = idx >> 3, j = idx & 7;
                o[(size_t)d * NKS + j] = xs[j * 65 + d];
            }
        } else {
            const int rg = row0 + row;
            ((float4*)(g_q + (size_t)rg * DD))[sl] = acc;
        }
    }

    grid_barrier(t);   // g_kT / g_q complete

    // =============== Phase B: split-K attention ============================
    // CTA = (b, 8-query tile qt, key-quarter ks): bid = ((b*64)+qt)*4 + ks
    float* S  = sm;             // [8][260] logits -> P in place
    float* QD = sm + QD_OFF;    // [64][16] (-q dup), dead after logits
    float* RED= sm + RED_OFF;   // aliases QD
    float* Mp = sm + MP_OFF;    // [8][4]
    int*   FL = (int*)(sm + FLAG_OFF);

    const int b  = bid >> 8;
    const int qt = (bid >> 2) & 63;
    const int ks = bid & 3;
    const int group = bid >> 2;        // (b,qt) in [0,256)

    // stage QD[d][2q..2q+1] = -q[qt*8+q][d]
#pragma unroll
    for (int u = 0; u < 4; u++) {
        int idx = u * 128 + t;          // 0..511
        int q = idx & 7, d = idx >> 3;
        float v = g_q[(size_t)(b * NQS + qt * 8 + q) * DD + d];
        QD[d * 16 + 2 * q + 0] = -v;
        QD[d * 16 + 2 * q + 1] = -v;
    }
    __syncthreads();

    // -------- logits: warp w covers local keys [w*64, w*64+64) ------------
    {
        const int jl = w * 64 + 2 * lane;
        const float* kp = g_kT + (size_t)b * DD * NKS + ks * 256 + jl;

        ull a0=0,a1=0,a2=0,a3=0,a4=0,a5=0,a6=0,a7=0;
#pragma unroll 8
        for (int d = 0; d < 64; d++) {
            ull k2 = *(const ull*)(kp + (size_t)d * NKS);
            const ulonglong2* nq = (const ulonglong2*)(QD + d * 16);
            ulonglong2 n0 = nq[0], n1 = nq[1], n2 = nq[2], n3 = nq[3];
            ull u_;
            ADD2(u_, k2, n0.x); u_ &= ABSM; ADD2(a0, a0, u_);
            ADD2(u_, k2, n0.y); u_ &= ABSM; ADD2(a1, a1, u_);
            ADD2(u_, k2, n1.x); u_ &= ABSM; ADD2(a2, a2, u_);
            ADD2(u_, k2, n1.y); u_ &= ABSM; ADD2(a3, a3, u_);
            ADD2(u_, k2, n2.x); u_ &= ABSM; ADD2(a4, a4, u_);
            ADD2(u_, k2, n2.y); u_ &= ABSM; ADD2(a5, a5, u_);
            ADD2(u_, k2, n3.x); u_ &= ABSM; ADD2(a6, a6, u_);
            ADD2(u_, k2, n3.y); u_ &= ABSM; ADD2(a7, a7, u_);
        }
        const ull accs[8] = {a0,a1,a2,a3,a4,a5,a6,a7};
        float m[8];
#pragma unroll
        for (int q = 0; q < 8; q++) {
            ull a = accs[q];
            float fl = -__uint_as_float((unsigned)a);
            float fh = -__uint_as_float((unsigned)(a >> 32));
            *(float2*)(S + q * S_STRIDE + jl) = make_float2(fl, fh);
            m[q] = fmaxf(fl, fh);
        }
#pragma unroll
        for (int q = 0; q < 8; q++) {
#pragma unroll
            for (int o = 16; o; o >>= 1)
                m[q] = fmaxf(m[q], __shfl_xor_sync(0xffffffffu, m[q], o));
        }
        if (lane == 0) {
#pragma unroll
            for (int q = 0; q < 8; q++) Mp[q * 4 + w] = m[q];
        }
    }
    __syncthreads();

    // -------- local softmax in place; (M, sum) -> global partials ---------
#pragma unroll
    for (int rr = 0; rr < 2; rr++) {
        const int row = w * 2 + rr;
        const float M = fmaxf(fmaxf(Mp[row * 4 + 0], Mp[row * 4 + 1]),
                              fmaxf(Mp[row * 4 + 2], Mp[row * 4 + 3]));
        float* Srow = S + row * S_STRIDE;
        float sum = 0.f;
#pragma unroll
        for (int it = 0; it < 8; it++) {
            int j = it * 32 + lane;
            float p = __expf(Srow[j] - M);
            Srow[j] = p;
            sum += p;
        }
#pragma unroll
        for (int o = 16; o; o >>= 1) sum += __shfl_xor_sync(0xffffffffu, sum, o);
        if (lane == 0) {
            g_pm[bid * 8 + row] = M;
            g_ps[bid * 8 + row] = sum;
        }
    }
    __syncthreads();

    // -------- partial O = P @ r: float4-amortized P loads -----------------
    {
        const int dg = lane & 15;
        const int qh = lane >> 4;
        const float* rb = rv + ((size_t)b * NKS + ks * 256 + w * 64) * DD + dg * 4;
        const float* Sb = S + (qh * 4) * S_STRIDE + w * 64;

        ull c00=0,c01=0,c10=0,c11=0,c20=0,c21=0,c30=0,c31=0;
#pragma unroll 4
        for (int c4 = 0; c4 < 16; c4++) {
            float4 P0 = *(const float4*)(Sb + 0 * S_STRIDE + c4 * 4);
            float4 P1 = *(const float4*)(Sb + 1 * S_STRIDE + c4 * 4);
            float4 P2 = *(const float4*)(Sb + 2 * S_STRIDE + c4 * 4);
            float4 P3 = *(const float4*)(Sb + 3 * S_STRIDE + c4 * 4);
#pragma unroll
            for (int e = 0; e < 4; e++) {
                const int kk = c4 * 4 + e;
                ulonglong2 r2 = *(const ulonglong2*)(rb + (size_t)kk * DD);
                float p0 = (e == 0) ? P0.x : (e == 1) ? P0.y : (e == 2) ? P0.z : P0.w;
                float p1 = (e == 0) ? P1.x : (e == 1) ? P1.y : (e == 2) ? P1.z : P1.w;
                float p2 = (e == 0) ? P2.x : (e == 1) ? P2.y : (e == 2) ? P2.z : P2.w;
                float p3 = (e == 0) ? P3.x : (e == 1) ? P3.y : (e == 2) ? P3.z : P3.w;
                ull pd;
                PACKDUP(pd, p0); FMA2(c00, pd, r2.x, c00); FMA2(c01, pd, r2.y, c01);
                PACKDUP(pd, p1); FMA2(c10, pd, r2.x, c10); FMA2(c11, pd, r2.y, c11);
                PACKDUP(pd, p2); FMA2(c20, pd, r2.x, c20); FMA2(c21, pd, r2.y, c21);
                PACKDUP(pd, p3); FMA2(c30, pd, r2.x, c30); FMA2(c31, pd, r2.y, c31);
            }
        }
        float4* R4 = (float4*)RED;
        const ull cc[4][2] = {{c00,c01},{c10,c11},{c20,c21},{c30,c31}};
#pragma unroll
        for (int i = 0; i < 4; i++) {
            int q = qh * 4 + i;
            R4[w * 128 + q * 16 + dg] =
                make_float4(__uint_as_float((unsigned)cc[i][0]),
                            __uint_as_float((unsigned)(cc[i][0] >> 32)),
                            __uint_as_float((unsigned)cc[i][1]),
                            __uint_as_float((unsigned)(cc[i][1] >> 32)));
        }
    }
    __syncthreads();

    // reduce 4 warps, store raw partial o to global
    {
        const int q = t >> 4, dd = t & 15;
        float4* R4 = (float4*)RED;
        float4 s = R4[q * 16 + dd];
#pragma unroll
        for (int g = 1; g < 4; g++) {
            float4 v = R4[g * 128 + q * 16 + dd];
            s.x += v.x; s.y += v.y; s.z += v.z; s.w += v.w;
        }
        ((float4*)(g_po + (size_t)bid * 512 + q * 64))[dd] = s;
    }
    __syncthreads();

    // =============== last-CTA combine (no second grid barrier) =============
    if (t == 0) {
        __threadfence();
        FL[0] = (atomicAdd(&g_done[group], 1) == 3) ? 1 : 0;
    }
    __syncthreads();

    if (FL[0]) {
        const int bb = group >> 6, qq = group & 63;
        const int q = t >> 4, dd = t & 15;
        const int base = group * 4;

        float m0 = g_pm[(base + 0) * 8 + q];
        float m1 = g_pm[(base + 1) * 8 + q];
        float m2 = g_pm[(base + 2) * 8 + q];
        float m3 = g_pm[(base + 3) * 8 + q];
        float M = fmaxf(fmaxf(m0, m1), fmaxf(m2, m3));
        float w0 = __expf(m0 - M), w1 = __expf(m1 - M);
        float w2 = __expf(m2 - M), w3 = __expf(m3 - M);
        float denom = w0 * g_ps[(base + 0) * 8 + q] + w1 * g_ps[(base + 1) * 8 + q]
                    + w2 * g_ps[(base + 2) * 8 + q] + w3 * g_ps[(base + 3) * 8 + q];

        float4 o0 = ((const float4*)(g_po + (size_t)(base + 0) * 512 + q * 64))[dd];
        float4 o1 = ((const float4*)(g_po + (size_t)(base + 1) * 512 + q * 64))[dd];
        float4 o2 = ((const float4*)(g_po + (size_t)(base + 2) * 512 + q * 64))[dd];
        float4 o3 = ((const float4*)(g_po + (size_t)(base + 3) * 512 + q * 64))[dd];

        const float li = 1.0f / denom;
        float4 o;
        o.x = (w0 * o0.x + w1 * o1.x + w2 * o2.x + w3 * o3.x) * li;
        o.y = (w0 * o0.y + w1 * o1.y + w2 * o2.y + w3 * o3.y) * li;
        o.z = (w0 * o0.z + w1 * o1.z + w2 * o2.z + w3 * o3.z) * li;
        o.w = (w0 * o0.w + w1 * o1.w + w2 * o2.w + w3 * o3.w) * li;

        ((float4*)(out + (size_t)(bb * NQS + qq * 8 + q) * DD))[dd] = o;

        if (t == 0) g_done[group] = 0;   // reset for graph replay
    }
}

// ---------------------------------------------------------------------------
extern "C" void kernel_launch(void* const* d_in, const int* in_sizes, int n_in,
                              void* d_out, int out_size)
{
    const float* x1  = (const float*)d_in[0];
    const float* x2  = (const float*)d_in[1];
    const float* r   = (const float*)d_in[2];
    const float* Wk1 = (const float*)d_in[3];
    const float* bk1 = (const float*)d_in[4];
    const float* Wk2 = (const float*)d_in[5];
    const float* bk2 = (const float*)d_in[6];
    const float* Wq1 = (const float*)d_in[7];
    const float* bq1 = (const float*)d_in[8];
    const float* Wq2 = (const float*)d_in[9];
    const float* bq2 = (const float*)d_in[10];
    float* out = (float*)d_out;

    cudaFuncSetAttribute(fused_kernel, cudaFuncAttributeMaxDynamicSharedMemorySize,
                         SMEM_BYTES);

    fused_kernel<<<NCTAS, 128, SMEM_BYTES>>>(
        x1, x2, r, Wk1, bk1, Wk2, bk2, Wq1, bq1, Wq2, bq2, out);
}

// round 15
// speedup vs baseline: 1.5667x; 1.0172x over previous
#include <cuda_runtime.h>

#define NB 4
#define NQS 512
#define NKS 1024
#define DD 64
#define NCTAS 1024

typedef unsigned long long ull;

#define ADD2(o,a,b)   asm("add.rn.f32x2 %0, %1, %2;" : "=l"(o) : "l"(a), "l"(b))
#define FMA2(o,a,b,c) asm("fma.rn.f32x2 %0, %1, %2, %3;" : "=l"(o) : "l"(a), "l"(b), "l"(c))
#define PACKDUP(o,f)  asm("mov.b64 %0, {%1, %1};" : "=l"(o) : "f"(f))
#define ABSM 0x7FFFFFFF7FFFFFFFULL

// ---- attn-phase smem (floats) ----
#define S_STRIDE 260
#define QD_OFF   2080              // [64 d][16] = 1024
#define RED_OFF  2080              // aliases QD (dead after logits)
#define MP_OFF   4128              // [8][4] warp maxima
#define FLAG_OFF 4160              // 1 int: last-CTA flag
#define SMEM_BYTES 21056           // sized by attn phase (mlp now needs only ~4KB)

// Scratch: k transposed per batch (kT[b][d][j]); q row-major.
__device__ __align__(16) float g_kT[NB * DD * NKS];
__device__ __align__(16) float g_q [NB * NQS * DD];
// split-K partials: per (b,qt,ks) CTA: o[8][64], m[8], s[8]
__device__ __align__(16) float g_po[NCTAS * 512];
__device__ float g_pm[NCTAS * 8];
__device__ float g_ps[NCTAS * 8];
// per-(b,qt) group completion counters (reset by combiner -> replay-safe)
__device__ int g_done[256];

// grid barrier (replay-safe)
__device__ unsigned g_cnt   = 0;
__device__ unsigned g_sense = 0;

__device__ __forceinline__ void grid_barrier(int t)
{
    __syncthreads();
    if (t == 0) {
        unsigned s = *(volatile unsigned*)&g_sense;
        __threadfence();
        if (atomicAdd(&g_cnt, 1) == NCTAS - 1) {
            g_cnt = 0;
            __threadfence();
            atomicAdd(&g_sense, 1);
        } else {
            while (*(volatile unsigned*)&g_sense == s) { __nanosleep(32); }
            __threadfence();
        }
    }
    __syncthreads();
}

__global__ __launch_bounds__(128, 8) void fused_kernel(
    const float* __restrict__ x1, const float* __restrict__ x2,
    const float* __restrict__ rv,
    const float* __restrict__ Wk1, const float* __restrict__ bk1,
    const float* __restrict__ Wk2, const float* __restrict__ bk2,
    const float* __restrict__ Wq1, const float* __restrict__ bq1,
    const float* __restrict__ Wq2, const float* __restrict__ bq2,
    float* __restrict__ out)
{
    extern __shared__ float sm[];
    const int bid  = blockIdx.x;
    const int t    = threadIdx.x;
    const int lane = t & 31;
    const int w    = t >> 5;

    // =============== Phase A: MLPs (768 CTAs x 8 rows) =====================
    // Weights read DIRECTLY from global (L1-resident, shared by co-resident
    // CTAs) — no smem staging, no W2-overwrite barrier.
    if (bid < 768) {
        float* xs  = sm;             // 8*65 = 520
        float* hs  = sm + 520;       // 520

        const bool keypath = bid < 512;
        const float *x, *W1, *b1, *W2, *b2;
        int row0;
        if (keypath) { x = x1; W1 = Wk1; b1 = bk1; W2 = Wk2; b2 = bk2; row0 = bid * 8; }
        else         { x = x2; W1 = Wq1; b1 = bq1; W2 = Wq2; b2 = bq2; row0 = (bid - 512) * 8; }

        {   // stage x: 8 rows x 16 float4 = 128, one per thread
            int rr = t >> 4, c = t & 15;
            float4 v = ((const float4*)(x + (size_t)(row0 + rr) * DD))[c];
            xs[rr * 65 + c * 4 + 0] = v.x;
            xs[rr * 65 + c * 4 + 1] = v.y;
            xs[rr * 65 + c * 4 + 2] = v.z;
            xs[rr * 65 + c * 4 + 3] = v.w;
        }
        __syncthreads();

        const int row = t >> 4, sl = t & 15;

        // layer 1 (weights via __ldg)
        float4 acc = __ldg((const float4*)b1 + sl);
        {
            const float* in1 = xs + row * 65;
            const float4* W1v = (const float4*)W1 + sl;
#pragma unroll 8
            for (int din = 0; din < 64; din++) {
                float xv = in1[din];
                float4 wv = __ldg(W1v + din * 16);
                acc.x = fmaf(xv, wv.x, acc.x);
                acc.y = fmaf(xv, wv.y, acc.y);
                acc.z = fmaf(xv, wv.z, acc.z);
                acc.w = fmaf(xv, wv.w, acc.w);
            }
        }
        {
            float* h = hs + row * 65 + sl * 4;
            h[0] = fmaxf(acc.x, 0.f); h[1] = fmaxf(acc.y, 0.f);
            h[2] = fmaxf(acc.z, 0.f); h[3] = fmaxf(acc.w, 0.f);
        }
        __syncthreads();

        // layer 2 (weights via __ldg; no staging barrier needed)
        acc = __ldg((const float4*)b2 + sl);
        {
            const float* in2 = hs + row * 65;
            const float4* W2v = (const float4*)W2 + sl;
#pragma unroll 8
            for (int din = 0; din < 64; din++) {
                float xv = in2[din];
                float4 wv = __ldg(W2v + din * 16);
                acc.x = fmaf(xv, wv.x, acc.x);
                acc.y = fmaf(xv, wv.y, acc.y);
                acc.z = fmaf(xv, wv.z, acc.z);
                acc.w = fmaf(xv, wv.w, acc.w);
            }
        }

        if (keypath) {
            __syncthreads();
            {   // stage output rows in xs (x no longer needed)
                float* o = xs + row * 65 + sl * 4;
                o[0] = acc.x; o[1] = acc.y; o[2] = acc.z; o[3] = acc.w;
            }
            __syncthreads();
            // transposed store g_kT[b][d][j0+j]
            const int bb = row0 >> 10;
            const int j0 = row0 & 1023;
            float* o = g_kT + (size_t)bb * DD * NKS + j0;
#pragma unroll
            for (int u = 0; u < 4; u++) {
                int idx = u * 128 + t;
                int d = idx >> 3, j = idx & 7;
                o[(size_t)d * NKS + j] = xs[j * 65 + d];
            }
        } else {
            const int rg = row0 + row;
            ((float4*)(g_q + (size_t)rg * DD))[sl] = acc;
        }
    }

    grid_barrier(t);   // g_kT / g_q complete

    // =============== Phase B: split-K attention (proven R10 layout) ========
    // CTA = (b, 8-query tile qt, key-quarter ks): bid = ((b*64)+qt)*4 + ks
    float* S  = sm;             // [8][260] logits -> P in place
    float* QD = sm + QD_OFF;    // [64][16] (-q dup), dead after logits
    float* RED= sm + RED_OFF;   // aliases QD
    float* Mp = sm + MP_OFF;    // [8][4]
    int*   FL = (int*)(sm + FLAG_OFF);

    const int b  = bid >> 8;
    const int qt = (bid >> 2) & 63;
    const int ks = bid & 3;
    const int group = bid >> 2;        // (b,qt) in [0,256)

    // stage QD[d][2q..2q+1] = -q[qt*8+q][d]
#pragma unroll
    for (int u = 0; u < 4; u++) {
        int idx = u * 128 + t;          // 0..511
        int q = idx & 7, d = idx >> 3;
        float v = g_q[(size_t)(b * NQS + qt * 8 + q) * DD + d];
        QD[d * 16 + 2 * q + 0] = -v;
        QD[d * 16 + 2 * q + 1] = -v;
    }
    __syncthreads();

    // -------- logits: warp w covers local keys [w*64, w*64+64) ------------
    {
        const int jl = w * 64 + 2 * lane;
        const float* kp = g_kT + (size_t)b * DD * NKS + ks * 256 + jl;

        ull a0=0,a1=0,a2=0,a3=0,a4=0,a5=0,a6=0,a7=0;
#pragma unroll 8
        for (int d = 0; d < 64; d++) {
            ull k2 = *(const ull*)(kp + (size_t)d * NKS);
            const ulonglong2* nq = (const ulonglong2*)(QD + d * 16);
            ulonglong2 n0 = nq[0], n1 = nq[1], n2 = nq[2], n3 = nq[3];
            ull u_;
            ADD2(u_, k2, n0.x); u_ &= ABSM; ADD2(a0, a0, u_);
            ADD2(u_, k2, n0.y); u_ &= ABSM; ADD2(a1, a1, u_);
            ADD2(u_, k2, n1.x); u_ &= ABSM; ADD2(a2, a2, u_);
            ADD2(u_, k2, n1.y); u_ &= ABSM; ADD2(a3, a3, u_);
            ADD2(u_, k2, n2.x); u_ &= ABSM; ADD2(a4, a4, u_);
            ADD2(u_, k2, n2.y); u_ &= ABSM; ADD2(a5, a5, u_);
            ADD2(u_, k2, n3.x); u_ &= ABSM; ADD2(a6, a6, u_);
            ADD2(u_, k2, n3.y); u_ &= ABSM; ADD2(a7, a7, u_);
        }
        const ull accs[8] = {a0,a1,a2,a3,a4,a5,a6,a7};
        float m[8];
#pragma unroll
        for (int q = 0; q < 8; q++) {
            ull a = accs[q];
            float fl = -__uint_as_float((unsigned)a);
            float fh = -__uint_as_float((unsigned)(a >> 32));
            *(float2*)(S + q * S_STRIDE + jl) = make_float2(fl, fh);
            m[q] = fmaxf(fl, fh);
        }
#pragma unroll
        for (int q = 0; q < 8; q++) {
#pragma unroll
            for (int o = 16; o; o >>= 1)
                m[q] = fmaxf(m[q], __shfl_xor_sync(0xffffffffu, m[q], o));
        }
        if (lane == 0) {
#pragma unroll
            for (int q = 0; q < 8; q++) Mp[q * 4 + w] = m[q];
        }
    }
    __syncthreads();

    // -------- local softmax in place; (M, sum) -> global partials ---------
#pragma unroll
    for (int rr = 0; rr < 2; rr++) {
        const int row = w * 2 + rr;
        const float M = fmaxf(fmaxf(Mp[row * 4 + 0], Mp[row * 4 + 1]),
                              fmaxf(Mp[row * 4 + 2], Mp[row * 4 + 3]));
        float* Srow = S + row * S_STRIDE;
        float sum = 0.f;
#pragma unroll
        for (int it = 0; it < 8; it++) {
            int j = it * 32 + lane;
            float p = __expf(Srow[j] - M);
            Srow[j] = p;
            sum += p;
        }
#pragma unroll
        for (int o = 16; o; o >>= 1) sum += __shfl_xor_sync(0xffffffffu, sum, o);
        if (lane == 0) {
            g_pm[bid * 8 + row] = M;
            g_ps[bid * 8 + row] = sum;
        }
    }
    __syncthreads();

    // -------- partial O = P @ r: float4-amortized P loads -----------------
    {
        const int dg = lane & 15;
        const int qh = lane >> 4;
        const float* rb = rv + ((size_t)b * NKS + ks * 256 + w * 64) * DD + dg * 4;
        const float* Sb = S + (qh * 4) * S_STRIDE + w * 64;

        ull c00=0,c01=0,c10=0,c11=0,c20=0,c21=0,c30=0,c31=0;
#pragma unroll 4
        for (int c4 = 0; c4 < 16; c4++) {
            float4 P0 = *(const float4*)(Sb + 0 * S_STRIDE + c4 * 4);
            float4 P1 = *(const float4*)(Sb + 1 * S_STRIDE + c4 * 4);
            float4 P2 = *(const float4*)(Sb + 2 * S_STRIDE + c4 * 4);
            float4 P3 = *(const float4*)(Sb + 3 * S_STRIDE + c4 * 4);
#pragma unroll
            for (int e = 0; e < 4; e++) {
                const int kk = c4 * 4 + e;
                ulonglong2 r2 = *(const ulonglong2*)(rb + (size_t)kk * DD);
                float p0 = (e == 0) ? P0.x : (e == 1) ? P0.y : (e == 2) ? P0.z : P0.w;
                float p1 = (e == 0) ? P1.x : (e == 1) ? P1.y : (e == 2) ? P1.z : P1.w;
                float p2 = (e == 0) ? P2.x : (e == 1) ? P2.y : (e == 2) ? P2.z : P2.w;
                float p3 = (e == 0) ? P3.x : (e == 1) ? P3.y : (e == 2) ? P3.z : P3.w;
                ull pd;
                PACKDUP(pd, p0); FMA2(c00, pd, r2.x, c00); FMA2(c01, pd, r2.y, c01);
                PACKDUP(pd, p1); FMA2(c10, pd, r2.x, c10); FMA2(c11, pd, r2.y, c11);
                PACKDUP(pd, p2); FMA2(c20, pd, r2.x, c20); FMA2(c21, pd, r2.y, c21);
                PACKDUP(pd, p3); FMA2(c30, pd, r2.x, c30); FMA2(c31, pd, r2.y, c31);
            }
        }
        float4* R4 = (float4*)RED;
        const ull cc[4][2] = {{c00,c01},{c10,c11},{c20,c21},{c30,c31}};
#pragma unroll
        for (int i = 0; i < 4; i++) {
            int q = qh * 4 + i;
            R4[w * 128 + q * 16 + dg] =
                make_float4(__uint_as_float((unsigned)cc[i][0]),
                            __uint_as_float((unsigned)(cc[i][0] >> 32)),
                            __uint_as_float((unsigned)cc[i][1]),
                            __uint_as_float((unsigned)(cc[i][1] >> 32)));
        }
    }
    __syncthreads();

    // reduce 4 warps, store raw partial o to global
    {
        const int q = t >> 4, dd = t & 15;
        float4* R4 = (float4*)RED;
        float4 s = R4[q * 16 + dd];
#pragma unroll
        for (int g = 1; g < 4; g++) {
            float4 v = R4[g * 128 + q * 16 + dd];
            s.x += v.x; s.y += v.y; s.z += v.z; s.w += v.w;
        }
        ((float4*)(g_po + (size_t)bid * 512 + q * 64))[dd] = s;
    }
    __syncthreads();

    // =============== last-CTA combine (no second grid barrier) =============
    if (t == 0) {
        __threadfence();
        FL[0] = (atomicAdd(&g_done[group], 1) == 3) ? 1 : 0;
    }
    __syncthreads();

    if (FL[0]) {
        const int bb = group >> 6, qq = group & 63;
        const int q = t >> 4, dd = t & 15;
        const int base = group * 4;

        float m0 = g_pm[(base + 0) * 8 + q];
        float m1 = g_pm[(base + 1) * 8 + q];
        float m2 = g_pm[(base + 2) * 8 + q];
        float m3 = g_pm[(base + 3) * 8 + q];
        float M = fmaxf(fmaxf(m0, m1), fmaxf(m2, m3));
        float w0 = __expf(m0 - M), w1 = __expf(m1 - M);
        float w2 = __expf(m2 - M), w3 = __expf(m3 - M);
        float denom = w0 * g_ps[(base + 0) * 8 + q] + w1 * g_ps[(base + 1) * 8 + q]
                    + w2 * g_ps[(base + 2) * 8 + q] + w3 * g_ps[(base + 3) * 8 + q];

        float4 o0 = ((const float4*)(g_po + (size_t)(base + 0) * 512 + q * 64))[dd];
        float4 o1 = ((const float4*)(g_po + (size_t)(base + 1) * 512 + q * 64))[dd];
        float4 o2 = ((const float4*)(g_po + (size_t)(base + 2) * 512 + q * 64))[dd];
        float4 o3 = ((const float4*)(g_po + (size_t)(base + 3) * 512 + q * 64))[dd];

        const float li = 1.0f / denom;
        float4 o;
        o.x = (w0 * o0.x + w1 * o1.x + w2 * o2.x + w3 * o3.x) * li;
        o.y = (w0 * o0.y + w1 * o1.y + w2 * o2.y + w3 * o3.y) * li;
        o.z = (w0 * o0.z + w1 * o1.z + w2 * o2.z + w3 * o3.z) * li;
        o.w = (w0 * o0.w + w1 * o1.w + w2 * o2.w + w3 * o3.w) * li;

        ((float4*)(out + (size_t)(bb * NQS + qq * 8 + q) * DD))[dd] = o;

        if (t == 0) g_done[group] = 0;   // reset for graph replay
    }
}

// ---------------------------------------------------------------------------
extern "C" void kernel_launch(void* const* d_in, const int* in_sizes, int n_in,
                              void* d_out, int out_size)
{
    const float* x1  = (const float*)d_in[0];
    const float* x2  = (const float*)d_in[1];
    const float* r   = (const float*)d_in[2];
    const float* Wk1 = (const float*)d_in[3];
    const float* bk1 = (const float*)d_in[4];
    const float* Wk2 = (const float*)d_in[5];
    const float* bk2 = (const float*)d_in[6];
    const float* Wq1 = (const float*)d_in[7];
    const float* bq1 = (const float*)d_in[8];
    const float* Wq2 = (const float*)d_in[9];
    const float* bq2 = (const float*)d_in[10];
    float* out = (float*)d_out;

    cudaFuncSetAttribute(fused_kernel, cudaFuncAttributeMaxDynamicSharedMemorySize,
                         SMEM_BYTES);

    fused_kernel<<<NCTAS, 128, SMEM_BYTES>>>(
        x1, x2, r, Wk1, bk1, Wk2, bk2, Wq1, bq1, Wq2, bq2, out);
}

// round 16
// speedup vs baseline: 1.6291x; 1.0398x over previous
#include <cuda_runtime.h>

#define NB 4
#define NQS 512
#define NKS 1024
#define DD 64
#define NCTAS 1024

typedef unsigned long long ull;

#define ADD2(o,a,b)   asm("add.rn.f32x2 %0, %1, %2;" : "=l"(o) : "l"(a), "l"(b))
#define FMA2(o,a,b,c) asm("fma.rn.f32x2 %0, %1, %2, %3;" : "=l"(o) : "l"(a), "l"(b), "l"(c))
#define PACKDUP(o,f)  asm("mov.b64 %0, {%1, %1};" : "=l"(o) : "f"(f))
#define ABSM 0x7FFFFFFF7FFFFFFFULL

// ---- attn-phase smem (floats) ----
#define S_STRIDE 260
#define QD_OFF   2080              // [64 d][16] = 1024
#define RED_OFF  2080              // aliases QD (dead after logits)
#define MP_OFF   4128              // [8][4] warp maxima
#define FLAG_OFF 4160              // 1 int: last-CTA flag
#define SMEM_BYTES 21056           // sized by attn phase

// Scratch: k transposed per batch (kT[b][d][j]).
__device__ __align__(16) float g_kT[NB * DD * NKS];
// q in QD layout, negated + pair-duplicated: g_qd[group][d][2q..2q+1]
__device__ __align__(16) float g_qd[256 * DD * 16];
// split-K partials: per (b,qt,ks) CTA: o[8][64], m[8], s[8]
__device__ __align__(16) float g_po[NCTAS * 512];
__device__ float g_pm[NCTAS * 8];
__device__ float g_ps[NCTAS * 8];
// per-(b,qt) group completion counters (reset by combiner -> replay-safe)
__device__ int g_done[256];

// grid barrier (replay-safe)
__device__ unsigned g_cnt   = 0;
__device__ unsigned g_sense = 0;

__device__ __forceinline__ void grid_barrier(int t)
{
    __syncthreads();
    if (t == 0) {
        unsigned s = *(volatile unsigned*)&g_sense;
        __threadfence();
        if (atomicAdd(&g_cnt, 1) == NCTAS - 1) {
            g_cnt = 0;
            __threadfence();
            atomicAdd(&g_sense, 1);
        } else {
            while (*(volatile unsigned*)&g_sense == s) { __nanosleep(32); }
            __threadfence();
        }
    }
    __syncthreads();
}

__global__ __launch_bounds__(128, 8) void fused_kernel(
    const float* __restrict__ x1, const float* __restrict__ x2,
    const float* __restrict__ rv,
    const float* __restrict__ Wk1, const float* __restrict__ bk1,
    const float* __restrict__ Wk2, const float* __restrict__ bk2,
    const float* __restrict__ Wq1, const float* __restrict__ bq1,
    const float* __restrict__ Wq2, const float* __restrict__ bq2,
    float* __restrict__ out)
{
    extern __shared__ float sm[];
    const int bid  = blockIdx.x;
    const int t    = threadIdx.x;
    const int lane = t & 31;
    const int w    = t >> 5;

    // =============== Phase A: MLPs (768 CTAs x 8 rows) =====================
    // Weights read directly via __ldg (L1-resident); no smem weight staging.
    if (bid < 768) {
        float* xs  = sm;             // 8*65 = 520
        float* hs  = sm + 520;       // 520

        const bool keypath = bid < 512;
        const float *x, *W1, *b1, *W2, *b2;
        int row0;
        if (keypath) { x = x1; W1 = Wk1; b1 = bk1; W2 = Wk2; b2 = bk2; row0 = bid * 8; }
        else         { x = x2; W1 = Wq1; b1 = bq1; W2 = Wq2; b2 = bq2; row0 = (bid - 512) * 8; }

        {   // stage x: 8 rows x 16 float4 = 128, one per thread
            int rr = t >> 4, c = t & 15;
            float4 v = ((const float4*)(x + (size_t)(row0 + rr) * DD))[c];
            xs[rr * 65 + c * 4 + 0] = v.x;
            xs[rr * 65 + c * 4 + 1] = v.y;
            xs[rr * 65 + c * 4 + 2] = v.z;
            xs[rr * 65 + c * 4 + 3] = v.w;
        }
        __syncthreads();

        const int row = t >> 4, sl = t & 15;

        // layer 1
        float4 acc = __ldg((const float4*)b1 + sl);
        {
            const float* in1 = xs + row * 65;
            const float4* W1v = (const float4*)W1 + sl;
#pragma unroll 8
            for (int din = 0; din < 64; din++) {
                float xv = in1[din];
                float4 wv = __ldg(W1v + din * 16);
                acc.x = fmaf(xv, wv.x, acc.x);
                acc.y = fmaf(xv, wv.y, acc.y);
                acc.z = fmaf(xv, wv.z, acc.z);
                acc.w = fmaf(xv, wv.w, acc.w);
            }
        }
        {
            float* h = hs + row * 65 + sl * 4;
            h[0] = fmaxf(acc.x, 0.f); h[1] = fmaxf(acc.y, 0.f);
            h[2] = fmaxf(acc.z, 0.f); h[3] = fmaxf(acc.w, 0.f);
        }
        __syncthreads();

        // layer 2
        acc = __ldg((const float4*)b2 + sl);
        {
            const float* in2 = hs + row * 65;
            const float4* W2v = (const float4*)W2 + sl;
#pragma unroll 8
            for (int din = 0; din < 64; din++) {
                float xv = in2[din];
                float4 wv = __ldg(W2v + din * 16);
                acc.x = fmaf(xv, wv.x, acc.x);
                acc.y = fmaf(xv, wv.y, acc.y);
                acc.z = fmaf(xv, wv.z, acc.z);
                acc.w = fmaf(xv, wv.w, acc.w);
            }
        }

        if (keypath) {
            __syncthreads();
            {   // stage output rows in xs (x no longer needed)
                float* o = xs + row * 65 + sl * 4;
                o[0] = acc.x; o[1] = acc.y; o[2] = acc.z; o[3] = acc.w;
            }
            __syncthreads();
            // transposed store g_kT[b][d][j0+j]
            const int bb = row0 >> 10;
            const int j0 = row0 & 1023;
            float* o = g_kT + (size_t)bb * DD * NKS + j0;
#pragma unroll
            for (int u = 0; u < 4; u++) {
                int idx = u * 128 + t;
                int d = idx >> 3, j = idx & 7;
                o[(size_t)d * NKS + j] = xs[j * 65 + d];
            }
        } else {
            // query path: write DIRECTLY in QD layout (negated + duplicated).
            // group g = bid - 512; thread (row,sl) owns q=row, dims sl*4..sl*4+3
            const int g = bid - 512;
            float* o = g_qd + (size_t)g * 1024;
            const float vv[4] = {acc.x, acc.y, acc.z, acc.w};
#pragma unroll
            for (int e = 0; e < 4; e++) {
                const int d = sl * 4 + e;
                float nv = -vv[e];
                o[d * 16 + 2 * row + 0] = nv;
                o[d * 16 + 2 * row + 1] = nv;
            }
        }
    }

    grid_barrier(t);   // g_kT / g_qd complete

    // =============== Phase B: split-K attention ============================
    // CTA = (b, 8-query tile qt, key-quarter ks): bid = ((b*64)+qt)*4 + ks
    float* S  = sm;             // [8][260] logits -> P in place
    float* QD = sm + QD_OFF;    // [64][16] (-q dup), dead after logits
    float* RED= sm + RED_OFF;   // aliases QD
    float* Mp = sm + MP_OFF;    // [8][4]
    int*   FL = (int*)(sm + FLAG_OFF);

    const int b  = bid >> 8;
    const int qt = (bid >> 2) & 63;
    const int ks = bid & 3;
    const int group = bid >> 2;        // (b,qt) in [0,256)

    // stage QD: straight float4 copy from g_qd (already negated + dup'd)
    {
        const float4* src = (const float4*)(g_qd + (size_t)group * 1024);
        float4* dst = (float4*)QD;
        dst[t]       = src[t];
        dst[t + 128] = src[t + 128];
    }
    __syncthreads();

    // -------- logits: warp w covers local keys [w*64, w*64+64) ------------
    {
        const int jl = w * 64 + 2 * lane;
        const float* kp = g_kT + (size_t)b * DD * NKS + ks * 256 + jl;

        ull a0=0,a1=0,a2=0,a3=0,a4=0,a5=0,a6=0,a7=0;
#pragma unroll 8
        for (int d = 0; d < 64; d++) {
            ull k2 = *(const ull*)(kp + (size_t)d * NKS);
            const ulonglong2* nq = (const ulonglong2*)(QD + d * 16);
            ulonglong2 n0 = nq[0], n1 = nq[1], n2 = nq[2], n3 = nq[3];
            ull u_;
            ADD2(u_, k2, n0.x); u_ &= ABSM; ADD2(a0, a0, u_);
            ADD2(u_, k2, n0.y); u_ &= ABSM; ADD2(a1, a1, u_);
            ADD2(u_, k2, n1.x); u_ &= ABSM; ADD2(a2, a2, u_);
            ADD2(u_, k2, n1.y); u_ &= ABSM; ADD2(a3, a3, u_);
            ADD2(u_, k2, n2.x); u_ &= ABSM; ADD2(a4, a4, u_);
            ADD2(u_, k2, n2.y); u_ &= ABSM; ADD2(a5, a5, u_);
            ADD2(u_, k2, n3.x); u_ &= ABSM; ADD2(a6, a6, u_);
            ADD2(u_, k2, n3.y); u_ &= ABSM; ADD2(a7, a7, u_);
        }
        const ull accs[8] = {a0,a1,a2,a3,a4,a5,a6,a7};
        float m[8];
#pragma unroll
        for (int q = 0; q < 8; q++) {
            ull a = accs[q];
            float fl = -__uint_as_float((unsigned)a);
            float fh = -__uint_as_float((unsigned)(a >> 32));
            *(float2*)(S + q * S_STRIDE + jl) = make_float2(fl, fh);
            m[q] = fmaxf(fl, fh);
        }
#pragma unroll
        for (int q = 0; q < 8; q++) {
#pragma unroll
            for (int o = 16; o; o >>= 1)
                m[q] = fmaxf(m[q], __shfl_xor_sync(0xffffffffu, m[q], o));
        }
        if (lane == 0) {
#pragma unroll
            for (int q = 0; q < 8; q++) Mp[q * 4 + w] = m[q];
        }
    }
    __syncthreads();

    // -------- local softmax in place; (M, sum) -> global partials ---------
#pragma unroll
    for (int rr = 0; rr < 2; rr++) {
        const int row = w * 2 + rr;
        const float M = fmaxf(fmaxf(Mp[row * 4 + 0], Mp[row * 4 + 1]),
                              fmaxf(Mp[row * 4 + 2], Mp[row * 4 + 3]));
        float* Srow = S + row * S_STRIDE;
        float sum = 0.f;
#pragma unroll
        for (int it = 0; it < 8; it++) {
            int j = it * 32 + lane;
            float p = __expf(Srow[j] - M);
            Srow[j] = p;
            sum += p;
        }
#pragma unroll
        for (int o = 16; o; o >>= 1) sum += __shfl_xor_sync(0xffffffffu, sum, o);
        if (lane == 0) {
            g_pm[bid * 8 + row] = M;
            g_ps[bid * 8 + row] = sum;
        }
    }
    __syncthreads();

    // -------- partial O = P @ r: float4-amortized P loads -----------------
    {
        const int dg = lane & 15;
        const int qh = lane >> 4;
        const float* rb = rv + ((size_t)b * NKS + ks * 256 + w * 64) * DD + dg * 4;
        const float* Sb = S + (qh * 4) * S_STRIDE + w * 64;

        ull c00=0,c01=0,c10=0,c11=0,c20=0,c21=0,c30=0,c31=0;
#pragma unroll 4
        for (int c4 = 0; c4 < 16; c4++) {
            float4 P0 = *(const float4*)(Sb + 0 * S_STRIDE + c4 * 4);
            float4 P1 = *(const float4*)(Sb + 1 * S_STRIDE + c4 * 4);
            float4 P2 = *(const float4*)(Sb + 2 * S_STRIDE + c4 * 4);
            float4 P3 = *(const float4*)(Sb + 3 * S_STRIDE + c4 * 4);
#pragma unroll
            for (int e = 0; e < 4; e++) {
                const int kk = c4 * 4 + e;
                ulonglong2 r2 = *(const ulonglong2*)(rb + (size_t)kk * DD);
                float p0 = (e == 0) ? P0.x : (e == 1) ? P0.y : (e == 2) ? P0.z : P0.w;
                float p1 = (e == 0) ? P1.x : (e == 1) ? P1.y : (e == 2) ? P1.z : P1.w;
                float p2 = (e == 0) ? P2.x : (e == 1) ? P2.y : (e == 2) ? P2.z : P2.w;
                float p3 = (e == 0) ? P3.x : (e == 1) ? P3.y : (e == 2) ? P3.z : P3.w;
                ull pd;
                PACKDUP(pd, p0); FMA2(c00, pd, r2.x, c00); FMA2(c01, pd, r2.y, c01);
                PACKDUP(pd, p1); FMA2(c10, pd, r2.x, c10); FMA2(c11, pd, r2.y, c11);
                PACKDUP(pd, p2); FMA2(c20, pd, r2.x, c20); FMA2(c21, pd, r2.y, c21);
                PACKDUP(pd, p3); FMA2(c30, pd, r2.x, c30); FMA2(c31, pd, r2.y, c31);
            }
        }
        float4* R4 = (float4*)RED;
        const ull cc[4][2] = {{c00,c01},{c10,c11},{c20,c21},{c30,c31}};
#pragma unroll
        for (int i = 0; i < 4; i++) {
            int q = qh * 4 + i;
            R4[w * 128 + q * 16 + dg] =
                make_float4(__uint_as_float((unsigned)cc[i][0]),
                            __uint_as_float((unsigned)(cc[i][0] >> 32)),
                            __uint_as_float((unsigned)cc[i][1]),
                            __uint_as_float((unsigned)(cc[i][1] >> 32)));
        }
    }
    __syncthreads();

    // reduce 4 warps, store raw partial o to global
    {
        const int q = t >> 4, dd = t & 15;
        float4* R4 = (float4*)RED;
        float4 s = R4[q * 16 + dd];
#pragma unroll
        for (int g = 1; g < 4; g++) {
            float4 v = R4[g * 128 + q * 16 + dd];
            s.x += v.x; s.y += v.y; s.z += v.z; s.w += v.w;
        }
        ((float4*)(g_po + (size_t)bid * 512 + q * 64))[dd] = s;
    }
    __syncthreads();

    // =============== last-CTA combine (no second grid barrier) =============
    if (t == 0) {
        __threadfence();
        FL[0] = (atomicAdd(&g_done[group], 1) == 3) ? 1 : 0;
    }
    __syncthreads();

    if (FL[0]) {
        const int bb = group >> 6, qq = group & 63;
        const int q = t >> 4, dd = t & 15;
        const int base = group * 4;

        float m0 = g_pm[(base + 0) * 8 + q];
        float m1 = g_pm[(base + 1) * 8 + q];
        float m2 = g_pm[(base + 2) * 8 + q];
        float m3 = g_pm[(base + 3) * 8 + q];
        float M = fmaxf(fmaxf(m0, m1), fmaxf(m2, m3));
        float w0 = __expf(m0 - M), w1 = __expf(m1 - M);
        float w2 = __expf(m2 - M), w3 = __expf(m3 - M);
        float denom = w0 * g_ps[(base + 0) * 8 + q] + w1 * g_ps[(base + 1) * 8 + q]
                    + w2 * g_ps[(base + 2) * 8 + q] + w3 * g_ps[(base + 3) * 8 + q];

        float4 o0 = ((const float4*)(g_po + (size_t)(base + 0) * 512 + q * 64))[dd];
        float4 o1 = ((const float4*)(g_po + (size_t)(base + 1) * 512 + q * 64))[dd];
        float4 o2 = ((const float4*)(g_po + (size_t)(base + 2) * 512 + q * 64))[dd];
        float4 o3 = ((const float4*)(g_po + (size_t)(base + 3) * 512 + q * 64))[dd];

        const float li = 1.0f / denom;
        float4 o;
        o.x = (w0 * o0.x + w1 * o1.x + w2 * o2.x + w3 * o3.x) * li;
        o.y = (w0 * o0.y + w1 * o1.y + w2 * o2.y + w3 * o3.y) * li;
        o.z = (w0 * o0.z + w1 * o1.z + w2 * o2.z + w3 * o3.z) * li;
        o.w = (w0 * o0.w + w1 * o1.w + w2 * o2.w + w3 * o3.w) * li;

        ((float4*)(out + (size_t)(bb * NQS + qq * 8 + q) * DD))[dd] = o;

        if (t == 0) g_done[group] = 0;   // reset for graph replay
    }
}

// ---------------------------------------------------------------------------
extern "C" void kernel_launch(void* const* d_in, const int* in_sizes, int n_in,
                              void* d_out, int out_size)
{
    const float* x1  = (const float*)d_in[0];
    const float* x2  = (const float*)d_in[1];
    const float* r   = (const float*)d_in[2];
    const float* Wk1 = (const float*)d_in[3];
    const float* bk1 = (const float*)d_in[4];
    const float* Wk2 = (const float*)d_in[5];
    const float* bk2 = (const float*)d_in[6];
    const float* Wq1 = (const float*)d_in[7];
    const float* bq1 = (const float*)d_in[8];
    const float* Wq2 = (const float*)d_in[9];
    const float* bq2 = (const float*)d_in[10];
    float* out = (float*)d_out;

    cudaFuncSetAttribute(fused_kernel, cudaFuncAttributeMaxDynamicSharedMemorySize,
                         SMEM_BYTES);

    fused_kernel<<<NCTAS, 128, SMEM_BYTES>>>(
        x1, x2, r, Wk1, bk1, Wk2, bk2, Wq1, bq1, Wq2, bq2, out);
}